// round 17
// baseline (speedup 1.0000x reference)
#include <cuda_runtime.h>
#include <cuda_bf16.h>

#define Bb   8
#define T    16
#define C    64
#define Hh   56
#define Ww   56
#define HW   3136          // 56*56
#define HW4  784           // HW/4
#define DIN  64            // 8*8 pooled
#define DOUT 32            // 2*d_t
#define NBC  512           // b*c
#define NCHUNK 1568        // 256-column chunks (= NBC*HW4/256)
#define NBLK 456           // persistent blocks = 152 SMs * 3 CTAs

// scratch: softmaxed attention [n][t][s], 512KB
__device__ float g_att[NBC * T * T];

// ---------------------------------------------------------------------------
// Kernel 1 (fused pool+att): R15 proven version. One block per n, 1024 thr,
// two warps per t-slice (4 serial bin-row rounds each), then q/k + logits +
// shuffle softmax from smem.
// ---------------------------------------------------------------------------
__global__ __launch_bounds__(1024)
void pool_att_kernel(const float* __restrict__ x,
                     const float* __restrict__ Wq, const float* __restrict__ bq,
                     const float* __restrict__ Wk, const float* __restrict__ bk)
{
    const int n    = blockIdx.x;        // n = b*C + c
    const int b    = n >> 6;
    const int c    = n & 63;
    const int tid  = threadIdx.x;
    const int w    = tid >> 5;          // warp 0..31
    const int t    = w >> 1;            // slice 0..15
    const int half = w & 1;             // which 4 bin-rows
    const int lane = tid & 31;

    __shared__ float scol[32][64];           // per-warp column sums, 8 KB
    __shared__ float flat[T][DIN];           // pooled features
    __shared__ float sWq[DIN * DOUT];        // 8 KB
    __shared__ float sWk[DIN * DOUT];        // 8 KB
    __shared__ float sq[T][DOUT + 1];
    __shared__ float sk[T][DOUT + 1];

    for (int i = tid; i < DIN * DOUT; i += 1024) {
        sWq[i] = Wq[i];
        sWk[i] = Wk[i];
    }

    const float* slice = x + ((size_t)(b * T + t) * C + c) * HW;
    #pragma unroll
    for (int r = 0; r < 4; ++r) {
        const int d1 = half * 4 + r;
        if (lane < 28) {
            const float2* rows = (const float2*)(slice + (7 * d1) * Ww);
            float2 s = make_float2(0.f, 0.f);
            #pragma unroll
            for (int dh = 0; dh < 7; ++dh) {
                const float2 v = rows[dh * (Ww / 2) + lane];
                s.x += v.x;
                s.y += v.y;
            }
            scol[w][2 * lane]     = s.x;
            scol[w][2 * lane + 1] = s.y;
        }
        __syncwarp();
        if (lane < 8) {
            const float* cs = &scol[w][7 * lane];
            float a0 = cs[0] + cs[1];
            float a1 = cs[2] + cs[3];
            float a2 = cs[4] + cs[5];
            a0 += cs[6];
            flat[t][d1 * 8 + lane] = (a0 + a1 + a2) * (1.f / 49.f);
        }
        __syncwarp();
    }
    __syncthreads();

    if (tid < 512) {
        const int tt = tid >> 5, j = tid & 31;
        float aq = bq[j];
        float ak = bk[j];
        #pragma unroll
        for (int d = 0; d < DIN; ++d) {
            const float f = flat[tt][d];
            aq = fmaf(f, sWq[d * DOUT + j], aq);
            ak = fmaf(f, sWk[d * DOUT + j], ak);
        }
        sq[tt][j] = aq;
        sk[tt][j] = ak;
    }
    __syncthreads();

    if (tid < 256) {
        const int i = tid >> 4, j = tid & 15;
        float s = 0.f;
        #pragma unroll
        for (int d = 0; d < DOUT; ++d)
            s = fmaf(sq[i][d], sk[j][d], s);
        s *= 0.25f;                          // 1/sqrt(16)

        float m = s;
        #pragma unroll
        for (int k = 8; k >= 1; k >>= 1)
            m = fmaxf(m, __shfl_xor_sync(0xffffffffu, m, k));
        float e = __expf(s - m);
        float ssum = e;
        #pragma unroll
        for (int k = 8; k >= 1; k >>= 1)
            ssum += __shfl_xor_sync(0xffffffffu, ssum, k);

        g_att[n * (T * T) + tid] = e * (1.f / ssum);
    }
}

// ---------------------------------------------------------------------------
// Kernel 2: PERSISTENT av. 456 blocks (1 wave at 3 CTAs/SM), each looping
// over ~3-4 column-chunks. Next chunk's 16 LDG.128 issue before the satt
// barriers, hiding load latency; no wave transitions. PDL pre-sync first
// loads; reversed-n; __stcs streaming stores.
// ---------------------------------------------------------------------------
__device__ __forceinline__ void chunk_addr(
    int chunk, int tid, const float* x, float* out,
    int& m, int& n0, const float4*& xb, float4*& ob)
{
    const int gid0 = chunk << 8;
    n0 = gid0 / HW4;
    const int gid = gid0 + tid;
    const int n   = gid / HW4;
    const int p4  = gid - n * HW4;
    m = n - n0;
    const int rn  = NBC - 1 - n;                    // reversed n
    const int b   = rn >> 6;
    const int c   = rn & 63;
    const int base = (b * T * C + c) * HW4 + p4;
    xb = (const float4*)x + base;
    ob = (float4*)out + base;
}

__global__ __launch_bounds__(256, 3)
void av_kernel(const float* __restrict__ x, float* __restrict__ out)
{
    const int tid = threadIdx.x;
    const int stride_s = C * HW4;                   // float4 stride per t/s

    __shared__ float satt[2][T * T];

    int chunk = blockIdx.x;
    int m, n0;
    const float4* xb;
    float4* ob;
    chunk_addr(chunk, tid, x, out, m, n0, xb, ob);

    // pre-sync: first chunk's 16 strided x loads (no dependency on att)
    float4 v[T];
    #pragma unroll
    for (int s = 0; s < T; ++s)
        v[s] = xb[s * stride_s];

    cudaGridDependencySynchronize();                // wait for g_att

    for (;;) {
        __syncthreads();                            // prior readers done
        #pragma unroll
        for (int i = tid; i < 2 * T * T; i += 256) {
            const int mm  = i >> 8;
            const int idx = i & 255;
            const int nn  = n0 + mm;
            satt[mm][idx] =
                (nn < NBC) ? g_att[(NBC - 1 - nn) * (T * T) + idx] : 0.f;
        }
        __syncthreads();

        const float* arow = satt[m];
        #pragma unroll
        for (int t = 0; t < T; ++t) {
            float4 a = make_float4(0.f, 0.f, 0.f, 0.f);
            #pragma unroll
            for (int s = 0; s < T; ++s) {
                const float w = arow[t * T + s];
                a.x = fmaf(w, v[s].x, a.x);
                a.y = fmaf(w, v[s].y, a.y);
                a.z = fmaf(w, v[s].z, a.z);
                a.w = fmaf(w, v[s].w, a.w);
            }
            __stcs(&ob[t * stride_s], a);           // streaming store
        }

        chunk += NBLK;
        if (chunk >= NCHUNK) break;

        // issue next chunk's loads before the staging barriers
        chunk_addr(chunk, tid, x, out, m, n0, xb, ob);
        #pragma unroll
        for (int s = 0; s < T; ++s)
            v[s] = xb[s * stride_s];
    }
}

// ---------------------------------------------------------------------------
extern "C" void kernel_launch(void* const* d_in, const int* in_sizes, int n_in,
                              void* d_out, int out_size)
{
    const float* x  = (const float*)d_in[0];
    const float* Wq = (const float*)d_in[1];
    const float* bq = (const float*)d_in[2];
    const float* Wk = (const float*)d_in[3];
    const float* bk = (const float*)d_in[4];
    float* out = (float*)d_out;

    pool_att_kernel<<<NBC, 1024>>>(x, Wq, bq, Wk, bk);

    cudaLaunchAttribute attr[1];
    attr[0].id = cudaLaunchAttributeProgrammaticStreamSerialization;
    attr[0].val.programmaticStreamSerializationAllowed = 1;

    cudaLaunchConfig_t cfg = {};
    cfg.gridDim  = dim3(NBLK);
    cfg.blockDim = dim3(256);
    cfg.dynamicSmemBytes = 0;
    cfg.stream = 0;
    cfg.attrs = attr;
    cfg.numAttrs = 1;
    cudaLaunchKernelEx(&cfg, av_kernel, x, out);
}